// round 5
// baseline (speedup 1.0000x reference)
#include <cuda_runtime.h>

#define H      768
#define DD     192
#define WIN    960          // H + DD
#define NCOMBO (8 * 17)     // 8 tokens x (16 dinuc states + 1 zero-pad state)
#define SEQ    2048
#define LN_EPS 1e-12f
#define TOK_PER_BLK 16

// Scratch (no cudaMalloc allowed)
__device__ float g_ytok[8 * H];        // token_emb @ W[:, :768]^T
__device__ float g_ydin[16 * H];       // dinuc_emb @ W[:, 768:960]^T
__device__ float g_table[NCOMBO * H];  // final layernormed rows
__device__ int   g_is64;               // 1 if input_ids is int64, 0 if int32

// ---------------------------------------------------------------------------
// Kernel 1 (v3): one block per output channel o. 768 blocks x 256 threads.
// Thread tid<240 loads ONE float4 of W[o][tid*4 .. tid*4+3] (coalesced; the
// only DRAM stream). Threads 0..191 cover the token slice (768 floats) and
// accumulate 8 dots; threads 192..239 cover the dinuc slice (192 floats) and
// accumulate 16 dots. Embeddings (36 KB total) are read directly -- L2-hot.
// Warp-shuffle + small smem reduction. Low regs/smem -> high occupancy; the
// 768 small blocks pipeline latency across the chip.
// ---------------------------------------------------------------------------
__global__ __launch_bounds__(256) void partial_kernel(
    const int*   __restrict__ ids32,
    const float* __restrict__ tok_emb,   // [8, 768]
    const float* __restrict__ din_emb,   // [16, 192]
    const float* __restrict__ W)         // [768, 960] row-major
{
    const int tid  = threadIdx.x;
    const int lane = tid & 31;
    const int warp = tid >> 5;
    const int o    = blockIdx.x;

    if (o == 0 && tid == 0) {
        int ok = 1;
        #pragma unroll 8
        for (int i = 0; i < 64; i++)
            if (ids32[2 * i + 1] != 0) ok = 0;
        g_is64 = ok;
    }

    __shared__ float s_tokred[6 * 8];    // warp-level partials, token part
    __shared__ float s_dinred[2 * 16];   // warp-level partials, dinuc part

    const float4* Wrow4 = reinterpret_cast<const float4*>(W + (size_t)o * WIN);
    const float4  wv    = (tid < 240) ? __ldg(&Wrow4[tid]) : make_float4(0.f, 0.f, 0.f, 0.f);

    if (warp < 6) {
        // ---- token part: element chunk [tid*4, tid*4+4) of 768 ----
        const float4* tok4 = reinterpret_cast<const float4*>(tok_emb);
        float acc[8];
        #pragma unroll
        for (int a = 0; a < 8; a++) {
            const float4 e = __ldg(&tok4[a * (H / 4) + tid]);
            acc[a] = wv.x * e.x + wv.y * e.y + wv.z * e.z + wv.w * e.w;
        }
        #pragma unroll
        for (int a = 0; a < 8; a++) {
            float v = acc[a];
            #pragma unroll
            for (int off = 16; off > 0; off >>= 1) v += __shfl_down_sync(0xffffffffu, v, off);
            if (lane == 0) s_tokred[warp * 8 + a] = v;
        }
    } else {
        // ---- dinuc part: thread j = tid-192 covers chunk [j*4, j*4+4) of 192 ----
        const int j = tid - 192;               // 0..63 (only 0..47 valid)
        const int jj = (j < 48) ? j : 0;       // clamp; wv==0 for invalid lanes
        const float4* din4 = reinterpret_cast<const float4*>(din_emb);
        float accd[16];
        #pragma unroll
        for (int d = 0; d < 16; d++) {
            const float4 e = __ldg(&din4[d * (DD / 4) + jj]);
            accd[d] = wv.x * e.x + wv.y * e.y + wv.z * e.z + wv.w * e.w;
        }
        #pragma unroll
        for (int d = 0; d < 16; d++) {
            float v = accd[d];
            #pragma unroll
            for (int off = 16; off > 0; off >>= 1) v += __shfl_down_sync(0xffffffffu, v, off);
            if (lane == 0) s_dinred[(warp - 6) * 16 + d] = v;
        }
    }
    __syncthreads();

    // ---- final reductions: 8 token sums (6 partials each), 16 dinuc (2 each) ----
    if (tid < 8) {
        float v = 0.f;
        #pragma unroll
        for (int w = 0; w < 6; w++) v += s_tokred[w * 8 + tid];
        g_ytok[tid * H + o] = v;
    } else if (tid < 24) {
        const int d = tid - 8;
        g_ydin[d * H + o] = s_dinred[d] + s_dinred[16 + d];
    }
}

// ---------------------------------------------------------------------------
// Kernel 2: build the 136-row layernormed table (two-pass mean/var).
// ---------------------------------------------------------------------------
__global__ __launch_bounds__(H) void table_kernel(
    const float* __restrict__ bias,
    const float* __restrict__ gamma,
    const float* __restrict__ beta)
{
    const int o    = threadIdx.x;
    const int a    = blockIdx.x / 17;
    const int d    = blockIdx.x % 17;
    const int lane = o & 31;
    const int warp = o >> 5;

    float x = g_ytok[a * H + o] + bias[o];
    if (d < 16) x += g_ydin[d * H + o];

    __shared__ float sred[32];
    __shared__ float s_mu, s_var;

    float v = x;
    #pragma unroll
    for (int off = 16; off > 0; off >>= 1) v += __shfl_down_sync(0xffffffffu, v, off);
    if (lane == 0) sred[warp] = v;
    __syncthreads();
    if (o < 32) {
        float t = (o < (H / 32)) ? sred[o] : 0.f;
        #pragma unroll
        for (int off = 16; off > 0; off >>= 1) t += __shfl_down_sync(0xffffffffu, t, off);
        if (o == 0) s_mu = t * (1.0f / H);
    }
    __syncthreads();

    const float dx = x - s_mu;
    v = dx * dx;
    #pragma unroll
    for (int off = 16; off > 0; off >>= 1) v += __shfl_down_sync(0xffffffffu, v, off);
    if (lane == 0) sred[warp] = v;
    __syncthreads();
    if (o < 32) {
        float t = (o < (H / 32)) ? sred[o] : 0.f;
        #pragma unroll
        for (int off = 16; off > 0; off >>= 1) t += __shfl_down_sync(0xffffffffu, t, off);
        if (o == 0) s_var = t * (1.0f / H);
    }
    __syncthreads();

    const float inv = rsqrtf(s_var + LN_EPS);
    g_table[blockIdx.x * H + o] = dx * inv * gamma[o] + beta[o];
}

// ---------------------------------------------------------------------------
// Kernel 3: gather. 16 tokens per block, 192 threads. Combos precomputed to
// shared, then an unrolled copy loop gives 16-deep load/store MLP per thread.
// ---------------------------------------------------------------------------
__global__ __launch_bounds__(192) void gather_kernel(
    const int* __restrict__ ids32,     // raw words; stride depends on g_is64
    float* __restrict__ out,
    int n_tokens)
{
    __shared__ int s_combo[TOK_PER_BLK];

    const int tid   = threadIdx.x;
    const int tbase = blockIdx.x * TOK_PER_BLK;

    if (tid < TOK_PER_BLK) {
        const int t = tbase + tid;
        int combo = 0;
        if (t < n_tokens) {
            const int stride = g_is64 ? 2 : 1;
            const int a = __ldg(&ids32[t * stride]);
            const int s = t & (SEQ - 1);
            if (s == SEQ - 1) {
                combo = a * 17 + 16;          // zero-pad dinuc state
            } else {
                const int nx = __ldg(&ids32[(t + 1) * stride]);
                const int dd = (a >= 4 && nx >= 4) ? ((a - 4) * 4 + (nx - 4)) : 0;
                combo = a * 17 + dd;
            }
        }
        s_combo[tid] = combo;
    }
    __syncthreads();

    const float4* tab4 = reinterpret_cast<const float4*>(g_table);
    float4*       out4 = reinterpret_cast<float4*>(out) + (size_t)tbase * (H / 4) + tid;

    #pragma unroll
    for (int i = 0; i < TOK_PER_BLK; i++) {
        const float4 v = __ldg(&tab4[s_combo[i] * (H / 4) + tid]);
        __stcs(out4, v);
        out4 += (H / 4);
    }
}

// ---------------------------------------------------------------------------
extern "C" void kernel_launch(void* const* d_in, const int* in_sizes, int n_in,
                              void* d_out, int out_size) {
    const int*   ids32   = (const int*)d_in[0];
    const float* tok_emb = (const float*)d_in[1];
    const float* din_emb = (const float*)d_in[2];
    const float* W       = (const float*)d_in[3];
    const float* bias    = (const float*)d_in[4];
    const float* gamma   = (const float*)d_in[5];
    const float* beta    = (const float*)d_in[6];
    float*       out     = (float*)d_out;

    const int n_tokens = in_sizes[0];                     // 65536
    const int nblk     = (n_tokens + TOK_PER_BLK - 1) / TOK_PER_BLK;

    partial_kernel<<<H, 256>>>(ids32, tok_emb, din_emb, W);
    table_kernel<<<NCOMBO, H>>>(bias, gamma, beta);
    gather_kernel<<<nblk, 192>>>(ids32, out, n_tokens);
}

// round 6
// speedup vs baseline: 1.1850x; 1.1850x over previous
#include <cuda_runtime.h>

#define H      768
#define DD     192
#define WIN    960          // H + DD
#define NCOMBO (8 * 17)     // 8 tokens x (16 dinuc states + 1 zero-pad state)
#define SEQ    2048
#define LN_EPS 1e-12f
#define TOK_PER_BLK 16

// Scratch (no cudaMalloc allowed)
__device__ float g_ytok[8 * H];        // token_emb @ W[:, :768]^T
__device__ float g_ydin[16 * H];       // dinuc_emb @ W[:, 768:960]^T
__device__ float g_table[NCOMBO * H];  // final layernormed rows
__device__ int   g_is64;               // 1 if input_ids is int64, 0 if int32

// ---------------------------------------------------------------------------
// Kernel 1 (v4): warp-per-output-channel, W staged through SHARED (not regs).
// 96 blocks x 256 threads. Block b stages W rows [b*8, b*8+8) (30 KB) into
// smem with 8 independent float4 loads per thread (full MLP, no register
// ceiling). Warp w then computes channel o = b*8+w: W from LDS.128,
// embeddings via __ldg (36 KB total, L1-hot after first touch).
// Block 0 / thread 0 also runs the int64-vs-int32 sniffer.
// ---------------------------------------------------------------------------
__global__ __launch_bounds__(256) void partial_kernel(
    const int*   __restrict__ ids32,
    const float* __restrict__ tok_emb,   // [8, 768]
    const float* __restrict__ din_emb,   // [16, 192]
    const float* __restrict__ W)         // [768, 960] row-major
{
    __shared__ float4 s_w[8 * (WIN / 4)];   // 8 rows x 240 float4 = 30 KB

    const int tid  = threadIdx.x;
    const int lane = tid & 31;
    const int warp = tid >> 5;

    if (blockIdx.x == 0 && tid == 0) {
        int ok = 1;
        #pragma unroll 8
        for (int i = 0; i < 64; i++)
            if (ids32[2 * i + 1] != 0) ok = 0;
        g_is64 = ok;
    }

    // ---- stage 8 W rows: 1920 float4, 8 independent loads/thread ----
    {
        const float4* Wb4 = reinterpret_cast<const float4*>(W) + (size_t)blockIdx.x * 8 * (WIN / 4);
        #pragma unroll
        for (int r = 0; r < 8; r++) {
            const int idx = r * 256 + tid;
            if (idx < 8 * (WIN / 4)) s_w[idx] = __ldg(&Wb4[idx]);
        }
    }
    __syncthreads();

    const int o = blockIdx.x * 8 + warp;
    const float4* wrow = &s_w[warp * (WIN / 4)];

    // ---- token part: 8 simultaneous dots of length 768 ----
    const float4* tok4 = reinterpret_cast<const float4*>(tok_emb);
    float acc[8];
    #pragma unroll
    for (int a = 0; a < 8; a++) acc[a] = 0.f;

    #pragma unroll
    for (int p = 0; p < 6; p++) {
        const float4 wv = wrow[p * 32 + lane];
        #pragma unroll
        for (int a = 0; a < 8; a++) {
            const float4 e = __ldg(&tok4[a * (H / 4) + p * 32 + lane]);
            acc[a] += wv.x * e.x + wv.y * e.y + wv.z * e.z + wv.w * e.w;
        }
    }
    #pragma unroll
    for (int a = 0; a < 8; a++) {
        float v = acc[a];
        #pragma unroll
        for (int off = 16; off > 0; off >>= 1) v += __shfl_down_sync(0xffffffffu, v, off);
        if (lane == 0) g_ytok[a * H + o] = v;
    }

    // ---- dinuc part: 16 simultaneous dots of length 192 (48 float4) ----
    const float4* din4 = reinterpret_cast<const float4*>(din_emb);
    float accd[16];
    #pragma unroll
    for (int d = 0; d < 16; d++) accd[d] = 0.f;

    {
        const float4 wv = wrow[(H / 4) + lane];
        #pragma unroll
        for (int d = 0; d < 16; d++) {
            const float4 e = __ldg(&din4[d * (DD / 4) + lane]);
            accd[d] += wv.x * e.x + wv.y * e.y + wv.z * e.z + wv.w * e.w;
        }
    }
    if (lane < 16) {
        const float4 wv = wrow[(H / 4) + 32 + lane];
        #pragma unroll
        for (int d = 0; d < 16; d++) {
            const float4 e = __ldg(&din4[d * (DD / 4) + 32 + lane]);
            accd[d] += wv.x * e.x + wv.y * e.y + wv.z * e.z + wv.w * e.w;
        }
    }
    #pragma unroll
    for (int d = 0; d < 16; d++) {
        float v = accd[d];
        #pragma unroll
        for (int off = 16; off > 0; off >>= 1) v += __shfl_down_sync(0xffffffffu, v, off);
        if (lane == 0) g_ydin[d * H + o] = v;
    }
}

// ---------------------------------------------------------------------------
// Kernel 2: build the 136-row layernormed table (two-pass mean/var).
// ---------------------------------------------------------------------------
__global__ __launch_bounds__(H) void table_kernel(
    const float* __restrict__ bias,
    const float* __restrict__ gamma,
    const float* __restrict__ beta)
{
    const int o    = threadIdx.x;
    const int a    = blockIdx.x / 17;
    const int d    = blockIdx.x % 17;
    const int lane = o & 31;
    const int warp = o >> 5;

    float x = g_ytok[a * H + o] + bias[o];
    if (d < 16) x += g_ydin[d * H + o];

    __shared__ float sred[32];
    __shared__ float s_mu, s_var;

    float v = x;
    #pragma unroll
    for (int off = 16; off > 0; off >>= 1) v += __shfl_down_sync(0xffffffffu, v, off);
    if (lane == 0) sred[warp] = v;
    __syncthreads();
    if (o < 32) {
        float t = (o < (H / 32)) ? sred[o] : 0.f;
        #pragma unroll
        for (int off = 16; off > 0; off >>= 1) t += __shfl_down_sync(0xffffffffu, t, off);
        if (o == 0) s_mu = t * (1.0f / H);
    }
    __syncthreads();

    const float dx = x - s_mu;
    v = dx * dx;
    #pragma unroll
    for (int off = 16; off > 0; off >>= 1) v += __shfl_down_sync(0xffffffffu, v, off);
    if (lane == 0) sred[warp] = v;
    __syncthreads();
    if (o < 32) {
        float t = (o < (H / 32)) ? sred[o] : 0.f;
        #pragma unroll
        for (int off = 16; off > 0; off >>= 1) t += __shfl_down_sync(0xffffffffu, t, off);
        if (o == 0) s_var = t * (1.0f / H);
    }
    __syncthreads();

    const float inv = rsqrtf(s_var + LN_EPS);
    g_table[blockIdx.x * H + o] = dx * inv * gamma[o] + beta[o];
}

// ---------------------------------------------------------------------------
// Kernel 3: gather. 16 tokens per block, 192 threads. Combos precomputed to
// shared, then an unrolled copy loop gives 16-deep load/store MLP per thread.
// ---------------------------------------------------------------------------
__global__ __launch_bounds__(192) void gather_kernel(
    const int* __restrict__ ids32,     // raw words; stride depends on g_is64
    float* __restrict__ out,
    int n_tokens)
{
    __shared__ int s_combo[TOK_PER_BLK];

    const int tid   = threadIdx.x;
    const int tbase = blockIdx.x * TOK_PER_BLK;

    if (tid < TOK_PER_BLK) {
        const int t = tbase + tid;
        int combo = 0;
        if (t < n_tokens) {
            const int stride = g_is64 ? 2 : 1;
            const int a = __ldg(&ids32[t * stride]);
            const int s = t & (SEQ - 1);
            if (s == SEQ - 1) {
                combo = a * 17 + 16;          // zero-pad dinuc state
            } else {
                const int nx = __ldg(&ids32[(t + 1) * stride]);
                const int dd = (a >= 4 && nx >= 4) ? ((a - 4) * 4 + (nx - 4)) : 0;
                combo = a * 17 + dd;
            }
        }
        s_combo[tid] = combo;
    }
    __syncthreads();

    const float4* tab4 = reinterpret_cast<const float4*>(g_table);
    float4*       out4 = reinterpret_cast<float4*>(out) + (size_t)tbase * (H / 4) + tid;

    #pragma unroll
    for (int i = 0; i < TOK_PER_BLK; i++) {
        const float4 v = __ldg(&tab4[s_combo[i] * (H / 4) + tid]);
        __stcs(out4, v);
        out4 += (H / 4);
    }
}

// ---------------------------------------------------------------------------
extern "C" void kernel_launch(void* const* d_in, const int* in_sizes, int n_in,
                              void* d_out, int out_size) {
    const int*   ids32   = (const int*)d_in[0];
    const float* tok_emb = (const float*)d_in[1];
    const float* din_emb = (const float*)d_in[2];
    const float* W       = (const float*)d_in[3];
    const float* bias    = (const float*)d_in[4];
    const float* gamma   = (const float*)d_in[5];
    const float* beta    = (const float*)d_in[6];
    float*       out     = (float*)d_out;

    const int n_tokens = in_sizes[0];                     // 65536
    const int nblk     = (n_tokens + TOK_PER_BLK - 1) / TOK_PER_BLK;

    partial_kernel<<<96, 256>>>(ids32, tok_emb, din_emb, W);
    table_kernel<<<NCOMBO, H>>>(bias, gamma, beta);
    gather_kernel<<<nblk, 192>>>(ids32, out, n_tokens);
}

// round 7
// speedup vs baseline: 1.2405x; 1.0468x over previous
#include <cuda_runtime.h>

#define H      768
#define DD     192
#define WIN    960          // H + DD
#define NCOMBO (8 * 17)
#define SEQ    2048
#define LN_EPS 1e-12f
#define TOK_PER_BLK 16

#define KC      96          // K-chunk size
#define NK_TOK  8           // 768 / 96
#define NK_DIN  2           // 192 / 96
#define NCT     24          // 768 channels / 32 per tile
#define SW_PITCH 33         // padded row stride (words) for transposed W tile

// Scratch (no cudaMalloc allowed)
__device__ float g_ptok[NK_TOK * 8 * H];    // K-partials, token part   [kc][a][o]
__device__ float g_pdin[NK_DIN * 16 * H];   // K-partials, dinuc part   [kc][d][o]
__device__ float g_table[NCOMBO * H];       // final layernormed rows
__device__ int   g_is64;                    // 1 if input_ids is int64

// ---------------------------------------------------------------------------
// Kernel 1 (v5): K-split tiled GEMM, thread-private accumulators, no shuffles.
// Blocks 0..191   : token part. b = kc*NCT + ct. 32 channels x 8 rows, K-chunk 96.
// Blocks 192..239 : dinuc part. 32 channels x 16 rows (2 rows/thread), K-chunk 96.
// Each block stages W chunk transposed (sW[k][ch], pitch 33 -> conflict-free
// reads) + E chunk, then each thread runs a 96-long smem dot. One coalesced
// partial store per accumulator. 240 blocks x 256 threads covers the chip.
// ---------------------------------------------------------------------------
__global__ __launch_bounds__(256) void partial_kernel(
    const int*   __restrict__ ids32,
    const float* __restrict__ tok_emb,   // [8, 768]
    const float* __restrict__ din_emb,   // [16, 192]
    const float* __restrict__ W)         // [768, 960] row-major
{
    __shared__ float  sW[KC * SW_PITCH];          // 12.7 KB, transposed W tile
    __shared__ float4 sE4[16 * (KC / 4)];         // up to 16 rows x 24 float4 = 6 KB

    const int tid = threadIdx.x;
    const int ch  = tid & 31;       // channel within tile
    const int rg  = tid >> 5;       // row group 0..7

    if (blockIdx.x == 0 && tid == 0) {
        int ok = 1;
        #pragma unroll 8
        for (int i = 0; i < 64; i++)
            if (ids32[2 * i + 1] != 0) ok = 0;
        g_is64 = ok;
    }

    const float* sE = reinterpret_cast<const float*>(sE4);
    const float4* W4 = reinterpret_cast<const float4*>(W);

    if (blockIdx.x < NK_TOK * NCT) {
        // ================= token part =================
        const int kc = blockIdx.x / NCT;          // 0..7
        const int ct = blockIdx.x % NCT;          // 0..23

        // stage W chunk transposed: 32 ch x 24 float4 = 768 float4, 3/thread
        #pragma unroll
        for (int t = 0; t < 3; t++) {
            const int idx = t * 256 + tid;        // 0..767
            const int c   = idx / (KC / 4);
            const int k4  = idx % (KC / 4);
            const float4 w = __ldg(&W4[(size_t)(ct * 32 + c) * (WIN / 4) + kc * (KC / 4) + k4]);
            float* dst = &sW[(k4 * 4) * SW_PITCH + c];
            dst[0 * SW_PITCH] = w.x;
            dst[1 * SW_PITCH] = w.y;
            dst[2 * SW_PITCH] = w.z;
            dst[3 * SW_PITCH] = w.w;
        }
        // stage E chunk: 8 rows x 24 float4 = 192 float4
        if (tid < 8 * (KC / 4)) {
            const int row = tid / (KC / 4);
            const int k4  = tid % (KC / 4);
            sE4[tid] = __ldg(&reinterpret_cast<const float4*>(tok_emb)[row * (H / 4) + kc * (KC / 4) + k4]);
        }
        __syncthreads();

        // dot: thread (ch, rg) -> row rg, channel ct*32+ch
        float acc = 0.f;
        #pragma unroll 8
        for (int k = 0; k < KC; k++)
            acc += sW[k * SW_PITCH + ch] * sE[rg * KC + k];

        g_ptok[(kc * 8 + rg) * H + ct * 32 + ch] = acc;
    } else {
        // ================= dinuc part =================
        const int b2 = blockIdx.x - NK_TOK * NCT;
        const int kc = b2 / NCT;                  // 0..1
        const int ct = b2 % NCT;                  // 0..23

        // stage W chunk (dinuc columns start at float4 offset H/4 = 192)
        #pragma unroll
        for (int t = 0; t < 3; t++) {
            const int idx = t * 256 + tid;
            const int c   = idx / (KC / 4);
            const int k4  = idx % (KC / 4);
            const float4 w = __ldg(&W4[(size_t)(ct * 32 + c) * (WIN / 4) + (H / 4) + kc * (KC / 4) + k4]);
            float* dst = &sW[(k4 * 4) * SW_PITCH + c];
            dst[0 * SW_PITCH] = w.x;
            dst[1 * SW_PITCH] = w.y;
            dst[2 * SW_PITCH] = w.z;
            dst[3 * SW_PITCH] = w.w;
        }
        // stage E chunk: 16 rows x 24 float4 = 384 float4, 2 loads/thread (guarded)
        #pragma unroll
        for (int t = 0; t < 2; t++) {
            const int idx = t * 256 + tid;
            if (idx < 16 * (KC / 4)) {
                const int row = idx / (KC / 4);
                const int k4  = idx % (KC / 4);
                sE4[idx] = __ldg(&reinterpret_cast<const float4*>(din_emb)[row * (DD / 4) + kc * (KC / 4) + k4]);
            }
        }
        __syncthreads();

        // thread (ch, rg) -> rows rg and rg+8
        float acc0 = 0.f, acc1 = 0.f;
        #pragma unroll 8
        for (int k = 0; k < KC; k++) {
            const float wv = sW[k * SW_PITCH + ch];
            acc0 += wv * sE[rg * KC + k];
            acc1 += wv * sE[(rg + 8) * KC + k];
        }

        g_pdin[(kc * 16 + rg) * H + ct * 32 + ch]       = acc0;
        g_pdin[(kc * 16 + rg + 8) * H + ct * 32 + ch]   = acc1;
    }
}

// ---------------------------------------------------------------------------
// Kernel 2: sum K-partials, then two-pass LayerNorm into the 136-row table.
// ---------------------------------------------------------------------------
__global__ __launch_bounds__(H) void table_kernel(
    const float* __restrict__ bias,
    const float* __restrict__ gamma,
    const float* __restrict__ beta)
{
    const int o    = threadIdx.x;
    const int a    = blockIdx.x / 17;
    const int d    = blockIdx.x % 17;
    const int lane = o & 31;
    const int warp = o >> 5;

    float x = bias[o];
    #pragma unroll
    for (int kc = 0; kc < NK_TOK; kc++) x += g_ptok[(kc * 8 + a) * H + o];
    if (d < 16) {
        x += g_pdin[d * H + o] + g_pdin[(16 + d) * H + o];
    }

    __shared__ float sred[32];
    __shared__ float s_mu, s_var;

    float v = x;
    #pragma unroll
    for (int off = 16; off > 0; off >>= 1) v += __shfl_down_sync(0xffffffffu, v, off);
    if (lane == 0) sred[warp] = v;
    __syncthreads();
    if (o < 32) {
        float t = (o < (H / 32)) ? sred[o] : 0.f;
        #pragma unroll
        for (int off = 16; off > 0; off >>= 1) t += __shfl_down_sync(0xffffffffu, t, off);
        if (o == 0) s_mu = t * (1.0f / H);
    }
    __syncthreads();

    const float dx = x - s_mu;
    v = dx * dx;
    #pragma unroll
    for (int off = 16; off > 0; off >>= 1) v += __shfl_down_sync(0xffffffffu, v, off);
    if (lane == 0) sred[warp] = v;
    __syncthreads();
    if (o < 32) {
        float t = (o < (H / 32)) ? sred[o] : 0.f;
        #pragma unroll
        for (int off = 16; off > 0; off >>= 1) t += __shfl_down_sync(0xffffffffu, t, off);
        if (o == 0) s_var = t * (1.0f / H);
    }
    __syncthreads();

    const float inv = rsqrtf(s_var + LN_EPS);
    g_table[blockIdx.x * H + o] = dx * inv * gamma[o] + beta[o];
}

// ---------------------------------------------------------------------------
// Kernel 3: gather. 16 tokens per block, 192 threads (unchanged — near floor).
// ---------------------------------------------------------------------------
__global__ __launch_bounds__(192) void gather_kernel(
    const int* __restrict__ ids32,
    float* __restrict__ out,
    int n_tokens)
{
    __shared__ int s_combo[TOK_PER_BLK];

    const int tid   = threadIdx.x;
    const int tbase = blockIdx.x * TOK_PER_BLK;

    if (tid < TOK_PER_BLK) {
        const int t = tbase + tid;
        int combo = 0;
        if (t < n_tokens) {
            const int stride = g_is64 ? 2 : 1;
            const int a = __ldg(&ids32[t * stride]);
            const int s = t & (SEQ - 1);
            if (s == SEQ - 1) {
                combo = a * 17 + 16;
            } else {
                const int nx = __ldg(&ids32[(t + 1) * stride]);
                const int dd = (a >= 4 && nx >= 4) ? ((a - 4) * 4 + (nx - 4)) : 0;
                combo = a * 17 + dd;
            }
        }
        s_combo[tid] = combo;
    }
    __syncthreads();

    const float4* tab4 = reinterpret_cast<const float4*>(g_table);
    float4*       out4 = reinterpret_cast<float4*>(out) + (size_t)tbase * (H / 4) + tid;

    #pragma unroll
    for (int i = 0; i < TOK_PER_BLK; i++) {
        const float4 v = __ldg(&tab4[s_combo[i] * (H / 4) + tid]);
        __stcs(out4, v);
        out4 += (H / 4);
    }
}

// ---------------------------------------------------------------------------
extern "C" void kernel_launch(void* const* d_in, const int* in_sizes, int n_in,
                              void* d_out, int out_size) {
    const int*   ids32   = (const int*)d_in[0];
    const float* tok_emb = (const float*)d_in[1];
    const float* din_emb = (const float*)d_in[2];
    const float* W       = (const float*)d_in[3];
    const float* bias    = (const float*)d_in[4];
    const float* gamma   = (const float*)d_in[5];
    const float* beta    = (const float*)d_in[6];
    float*       out     = (float*)d_out;

    const int n_tokens = in_sizes[0];
    const int nblk     = (n_tokens + TOK_PER_BLK - 1) / TOK_PER_BLK;

    partial_kernel<<<NK_TOK * NCT + NK_DIN * NCT, 256>>>(ids32, tok_emb, din_emb, W);
    table_kernel<<<NCOMBO, H>>>(bias, gamma, beta);
    gather_kernel<<<nblk, 192>>>(ids32, out, n_tokens);
}

// round 8
// speedup vs baseline: 1.2486x; 1.0065x over previous
#include <cuda_runtime.h>

#define H      768
#define DD     192
#define WIN    960          // H + DD
#define NCOMBO (8 * 17)
#define SEQ    2048
#define LN_EPS 1e-12f
#define TOK_PER_BLK 16

#define KC      48          // K-chunk size
#define KC4     (KC / 4)    // 12 float4 per chunk-row
#define NK_TOK  16          // 768 / 48
#define NK_DIN  4           // 192 / 48
#define NCT     24          // 768 channels / 32 per tile
#define SW_PITCH 33         // padded row stride (words) for transposed W tile

// Scratch (no cudaMalloc allowed)
__device__ float g_ptok[NK_TOK * 8 * H];    // K-partials, token part   [kc][a][o]
__device__ float g_pdin[NK_DIN * 16 * H];   // K-partials, dinuc part   [kc][d][o]
__device__ float g_table[NCOMBO * H];       // final layernormed rows
__device__ int   g_is64;                    // 1 if input_ids is int64

// ---------------------------------------------------------------------------
// Kernel 1 (v6): K-split tiled GEMM, KC=48, 480 blocks x 256 threads.
// Blocks 0..383   : token part. b = kc*NCT + ct (kc<16). 32 ch x 8 rows.
// Blocks 384..479 : dinuc part. kc<4. 32 ch x 16 rows (2 rows/thread).
// ~10 KB smem -> 4+ blocks/SM resident; short 48-iter dots pipeline across
// overlapping waves instead of one long latency-bound wave.
// ---------------------------------------------------------------------------
__global__ __launch_bounds__(256) void partial_kernel(
    const int*   __restrict__ ids32,
    const float* __restrict__ tok_emb,   // [8, 768]
    const float* __restrict__ din_emb,   // [16, 192]
    const float* __restrict__ W)         // [768, 960] row-major
{
    __shared__ float  sW[KC * SW_PITCH];      // 6.3 KB, transposed W tile
    __shared__ float4 sE4[16 * KC4];          // up to 16 rows x 12 float4 = 3 KB

    const int tid = threadIdx.x;
    const int ch  = tid & 31;       // channel within tile
    const int rg  = tid >> 5;       // row group 0..7

    if (blockIdx.x == 0 && tid == 0) {
        int ok = 1;
        #pragma unroll 8
        for (int i = 0; i < 64; i++)
            if (ids32[2 * i + 1] != 0) ok = 0;
        g_is64 = ok;
    }

    const float*  sE = reinterpret_cast<const float*>(sE4);
    const float4* W4 = reinterpret_cast<const float4*>(W);

    if (blockIdx.x < NK_TOK * NCT) {
        // ================= token part =================
        const int kc = blockIdx.x / NCT;          // 0..15
        const int ct = blockIdx.x % NCT;          // 0..23

        // stage W chunk transposed: 32 ch x 12 float4 = 384 float4
        #pragma unroll
        for (int t = 0; t < 2; t++) {
            const int idx = t * 256 + tid;
            if (idx < 32 * KC4) {
                const int c  = idx / KC4;
                const int k4 = idx % KC4;
                const float4 w = __ldg(&W4[(size_t)(ct * 32 + c) * (WIN / 4) + kc * KC4 + k4]);
                float* dst = &sW[(k4 * 4) * SW_PITCH + c];
                dst[0 * SW_PITCH] = w.x;
                dst[1 * SW_PITCH] = w.y;
                dst[2 * SW_PITCH] = w.z;
                dst[3 * SW_PITCH] = w.w;
            }
        }
        // stage E chunk: 8 rows x 12 float4 = 96 float4
        if (tid < 8 * KC4) {
            const int row = tid / KC4;
            const int k4  = tid % KC4;
            sE4[tid] = __ldg(&reinterpret_cast<const float4*>(tok_emb)[row * (H / 4) + kc * KC4 + k4]);
        }
        __syncthreads();

        float acc = 0.f;
        #pragma unroll 8
        for (int k = 0; k < KC; k++)
            acc += sW[k * SW_PITCH + ch] * sE[rg * KC + k];

        g_ptok[(kc * 8 + rg) * H + ct * 32 + ch] = acc;
    } else {
        // ================= dinuc part =================
        const int b2 = blockIdx.x - NK_TOK * NCT;
        const int kc = b2 / NCT;                  // 0..3
        const int ct = b2 % NCT;                  // 0..23

        #pragma unroll
        for (int t = 0; t < 2; t++) {
            const int idx = t * 256 + tid;
            if (idx < 32 * KC4) {
                const int c  = idx / KC4;
                const int k4 = idx % KC4;
                const float4 w = __ldg(&W4[(size_t)(ct * 32 + c) * (WIN / 4) + (H / 4) + kc * KC4 + k4]);
                float* dst = &sW[(k4 * 4) * SW_PITCH + c];
                dst[0 * SW_PITCH] = w.x;
                dst[1 * SW_PITCH] = w.y;
                dst[2 * SW_PITCH] = w.z;
                dst[3 * SW_PITCH] = w.w;
            }
        }
        // stage E chunk: 16 rows x 12 float4 = 192 float4
        if (tid < 16 * KC4) {
            const int row = tid / KC4;
            const int k4  = tid % KC4;
            sE4[tid] = __ldg(&reinterpret_cast<const float4*>(din_emb)[row * (DD / 4) + kc * KC4 + k4]);
        }
        __syncthreads();

        float acc0 = 0.f, acc1 = 0.f;
        #pragma unroll 8
        for (int k = 0; k < KC; k++) {
            const float wv = sW[k * SW_PITCH + ch];
            acc0 += wv * sE[rg * KC + k];
            acc1 += wv * sE[(rg + 8) * KC + k];
        }

        g_pdin[(kc * 16 + rg) * H + ct * 32 + ch]     = acc0;
        g_pdin[(kc * 16 + rg + 8) * H + ct * 32 + ch] = acc1;
    }
}

// ---------------------------------------------------------------------------
// Kernel 2: sum K-partials, then two-pass LayerNorm into the 136-row table.
// ---------------------------------------------------------------------------
__global__ __launch_bounds__(H) void table_kernel(
    const float* __restrict__ bias,
    const float* __restrict__ gamma,
    const float* __restrict__ beta)
{
    const int o    = threadIdx.x;
    const int a    = blockIdx.x / 17;
    const int d    = blockIdx.x % 17;
    const int lane = o & 31;
    const int warp = o >> 5;

    float x = bias[o];
    #pragma unroll
    for (int kc = 0; kc < NK_TOK; kc++) x += g_ptok[(kc * 8 + a) * H + o];
    if (d < 16) {
        #pragma unroll
        for (int kc = 0; kc < NK_DIN; kc++) x += g_pdin[(kc * 16 + d) * H + o];
    }

    __shared__ float sred[32];
    __shared__ float s_mu, s_var;

    float v = x;
    #pragma unroll
    for (int off = 16; off > 0; off >>= 1) v += __shfl_down_sync(0xffffffffu, v, off);
    if (lane == 0) sred[warp] = v;
    __syncthreads();
    if (o < 32) {
        float t = (o < (H / 32)) ? sred[o] : 0.f;
        #pragma unroll
        for (int off = 16; off > 0; off >>= 1) t += __shfl_down_sync(0xffffffffu, t, off);
        if (o == 0) s_mu = t * (1.0f / H);
    }
    __syncthreads();

    const float dx = x - s_mu;
    v = dx * dx;
    #pragma unroll
    for (int off = 16; off > 0; off >>= 1) v += __shfl_down_sync(0xffffffffu, v, off);
    if (lane == 0) sred[warp] = v;
    __syncthreads();
    if (o < 32) {
        float t = (o < (H / 32)) ? sred[o] : 0.f;
        #pragma unroll
        for (int off = 16; off > 0; off >>= 1) t += __shfl_down_sync(0xffffffffu, t, off);
        if (o == 0) s_var = t * (1.0f / H);
    }
    __syncthreads();

    const float inv = rsqrtf(s_var + LN_EPS);
    g_table[blockIdx.x * H + o] = dx * inv * gamma[o] + beta[o];
}

// ---------------------------------------------------------------------------
// Kernel 3: gather. 16 tokens per block, 192 threads (unchanged — near floor).
// ---------------------------------------------------------------------------
__global__ __launch_bounds__(192) void gather_kernel(
    const int* __restrict__ ids32,
    float* __restrict__ out,
    int n_tokens)
{
    __shared__ int s_combo[TOK_PER_BLK];

    const int tid   = threadIdx.x;
    const int tbase = blockIdx.x * TOK_PER_BLK;

    if (tid < TOK_PER_BLK) {
        const int t = tbase + tid;
        int combo = 0;
        if (t < n_tokens) {
            const int stride = g_is64 ? 2 : 1;
            const int a = __ldg(&ids32[t * stride]);
            const int s = t & (SEQ - 1);
            if (s == SEQ - 1) {
                combo = a * 17 + 16;
            } else {
                const int nx = __ldg(&ids32[(t + 1) * stride]);
                const int dd = (a >= 4 && nx >= 4) ? ((a - 4) * 4 + (nx - 4)) : 0;
                combo = a * 17 + dd;
            }
        }
        s_combo[tid] = combo;
    }
    __syncthreads();

    const float4* tab4 = reinterpret_cast<const float4*>(g_table);
    float4*       out4 = reinterpret_cast<float4*>(out) + (size_t)tbase * (H / 4) + tid;

    #pragma unroll
    for (int i = 0; i < TOK_PER_BLK; i++) {
        const float4 v = __ldg(&tab4[s_combo[i] * (H / 4) + tid]);
        __stcs(out4, v);
        out4 += (H / 4);
    }
}

// ---------------------------------------------------------------------------
extern "C" void kernel_launch(void* const* d_in, const int* in_sizes, int n_in,
                              void* d_out, int out_size) {
    const int*   ids32   = (const int*)d_in[0];
    const float* tok_emb = (const float*)d_in[1];
    const float* din_emb = (const float*)d_in[2];
    const float* W       = (const float*)d_in[3];
    const float* bias    = (const float*)d_in[4];
    const float* gamma   = (const float*)d_in[5];
    const float* beta    = (const float*)d_in[6];
    float*       out     = (float*)d_out;

    const int n_tokens = in_sizes[0];
    const int nblk     = (n_tokens + TOK_PER_BLK - 1) / TOK_PER_BLK;

    partial_kernel<<<NK_TOK * NCT + NK_DIN * NCT, 256>>>(ids32, tok_emb, din_emb, W);
    table_kernel<<<NCOMBO, H>>>(bias, gamma, beta);
    gather_kernel<<<nblk, 192>>>(ids32, out, n_tokens);
}